// round 3
// baseline (speedup 1.0000x reference)
#include <cuda_runtime.h>
#include <math.h>

#define F 64
#define N_CAP   50176
#define TOT_CAP 852992   // E + N with margin
#define RS 68            // smem row stride (floats): 272B, keeps float4 rows 16B-aligned

typedef unsigned long long u64;

// ---------------- packed f32x2 helpers (Blackwell FFMA2) ----------------
__device__ __forceinline__ u64 ffma2(u64 a, u64 b, u64 c) {
    u64 d;
    asm("fma.rn.f32x2 %0, %1, %2, %3;" : "=l"(d) : "l"(a), "l"(b), "l"(c));
    return d;
}
__device__ __forceinline__ u64 pack2s(float x) {          // (x, x)
    u64 r; asm("mov.b64 %0, {%1, %1};" : "=l"(r) : "f"(x)); return r;
}
__device__ __forceinline__ u64 pack2(float x, float y) {  // (x, y)
    u64 r; asm("mov.b64 %0, {%1, %2};" : "=l"(r) : "f"(x), "f"(y)); return r;
}
__device__ __forceinline__ float2 unpack2(u64 v) {
    float2 f; asm("mov.b64 {%0, %1}, %2;" : "=f"(f.x), "=f"(f.y) : "l"(v)); return f;
}

// ---------------- device scratch ----------------
__device__ float g_asrc[N_CAP * F];
__device__ float g_adst[N_CAP * F];
__device__ float g_v   [N_CAP * F];
__device__ float g_ssum[N_CAP * F];
__device__ float g_oacc[N_CAP * F];
__device__ float g_eexp[TOT_CAP * F];   // exp(alpha) per edge
__device__ float g_tvd [TOT_CAP * F];   // v[src] + delta per edge

// ---------------- 2x8 f32x2-tiled 64x64x64 smem GEMM (accumulating) ----------------
// Thread computes rows {r0, r0+1} x cols [c0, c0+8) ; acc[2][4] packed f32x2.
__device__ __forceinline__ void gemm64_x2(const float* __restrict__ As,  // [64][RS]
                                          const float* __restrict__ Bs,  // [64][64]
                                          int r0, int c0, u64 acc[2][4])
{
#pragma unroll 8
    for (int k = 0; k < 64; k++) {
        const float* bp = Bs + k * 64 + c0;
        ulonglong2 bA = *(const ulonglong2*)(bp);        // cols c0..c0+3
        ulonglong2 bB = *(const ulonglong2*)(bp + 4);    // cols c0+4..c0+7
        u64 a0 = pack2s(As[(r0    ) * RS + k]);
        u64 a1 = pack2s(As[(r0 + 1) * RS + k]);
        acc[0][0] = ffma2(a0, bA.x, acc[0][0]);
        acc[0][1] = ffma2(a0, bA.y, acc[0][1]);
        acc[0][2] = ffma2(a0, bB.x, acc[0][2]);
        acc[0][3] = ffma2(a0, bB.y, acc[0][3]);
        acc[1][0] = ffma2(a1, bA.x, acc[1][0]);
        acc[1][1] = ffma2(a1, bA.y, acc[1][1]);
        acc[1][2] = ffma2(a1, bB.x, acc[1][2]);
        acc[1][3] = ffma2(a1, bB.y, acc[1][3]);
    }
}

__device__ __forceinline__ void init_bias(const float* b, int c0, u64 acc[2][4]) {
#pragma unroll
    for (int j = 0; j < 4; j++) {
        u64 v = pack2(b[c0 + 2 * j], b[c0 + 2 * j + 1]);
        acc[0][j] = v; acc[1][j] = v;
    }
}
__device__ __forceinline__ void init_zero(u64 acc[2][4]) {
#pragma unroll
    for (int j = 0; j < 4; j++) { acc[0][j] = 0ull; acc[1][j] = 0ull; }
}

// relu + store row pair into smem [64][RS]
__device__ __forceinline__ void relu_store_smem(float* Out, int r0, int c0, u64 acc[2][4]) {
#pragma unroll
    for (int i = 0; i < 2; i++)
#pragma unroll
        for (int j = 0; j < 4; j++) {
            float2 f = unpack2(acc[i][j]);
            *(float2*)(Out + (r0 + i) * RS + c0 + 2 * j) =
                make_float2(fmaxf(f.x, 0.f), fmaxf(f.y, 0.f));
        }
}

// store row pair (raw) to global [.,64]
__device__ __forceinline__ void store_gmem(float* Out, int row, int c0, u64 a[4]) {
    float2 f0 = unpack2(a[0]), f1 = unpack2(a[1]), f2 = unpack2(a[2]), f3 = unpack2(a[3]);
    *(float4*)(Out + (size_t)row * 64 + c0)     = make_float4(f0.x, f0.y, f1.x, f1.y);
    *(float4*)(Out + (size_t)row * 64 + c0 + 4) = make_float4(f2.x, f2.y, f3.x, f3.y);
}

// ---------------- K1: h = relu(x@Win+b); a_src=h@Wsrc; a_dst=h@Wdst; v=h@Wlin ----------------
__global__ void __launch_bounds__(256) k_proj(
    const float* __restrict__ x,
    const float* __restrict__ Win, const float* __restrict__ bin,
    const float* __restrict__ Wsrc, const float* __restrict__ Wdst,
    const float* __restrict__ Wlin, int N)
{
    extern __shared__ float sm[];
    float* sWin = sm;
    float* sWs  = sWin + 4096;
    float* sWd  = sWs  + 4096;
    float* sWl  = sWd  + 4096;
    float* sb   = sWl  + 4096;
    float* xs   = sb + 64;          // [64][RS]
    float* hs   = xs + 64 * RS;     // [64][RS]
    const int tid = threadIdx.x;

    for (int i = tid; i < 4096; i += 256) {
        sWin[i] = Win[i]; sWs[i] = Wsrc[i]; sWd[i] = Wdst[i]; sWl[i] = Wlin[i];
    }
    if (tid < 64) sb[tid] = bin[tid];

    const int base = blockIdx.x * 64;
    for (int i = tid; i < 1024; i += 256) {
        int r = i >> 4, c4 = (i & 15) << 2;
        int row = base + r;
        float4 v = (row < N) ? *(const float4*)(x + (size_t)row * 64 + c4)
                             : make_float4(0.f, 0.f, 0.f, 0.f);
        *(float4*)(xs + r * RS + c4) = v;
    }
    __syncthreads();

    const int r0 = (tid >> 3) * 2, c0 = (tid & 7) * 8;
    u64 acc[2][4];

    // h
    init_bias(sb, c0, acc);
    gemm64_x2(xs, sWin, r0, c0, acc);
    relu_store_smem(hs, r0, c0, acc);
    __syncthreads();

    // a_src
    init_zero(acc);
    gemm64_x2(hs, sWs, r0, c0, acc);
#pragma unroll
    for (int i = 0; i < 2; i++) { int row = base + r0 + i; if (row < N) store_gmem(g_asrc, row, c0, acc[i]); }

    // a_dst
    init_zero(acc);
    gemm64_x2(hs, sWd, r0, c0, acc);
#pragma unroll
    for (int i = 0; i < 2; i++) { int row = base + r0 + i; if (row < N) store_gmem(g_adst, row, c0, acc[i]); }

    // v
    init_zero(acc);
    gemm64_x2(hs, sWl, r0, c0, acc);
#pragma unroll
    for (int i = 0; i < 2; i++) { int row = base + r0 + i; if (row < N) store_gmem(g_v, row, c0, acc[i]); }
}

// ---------------- K2: per-edge MLPs, exp(alpha), scatter-sum of exp ----------------
__global__ void __launch_bounds__(256, 2) k_edge1(
    const float* __restrict__ pos, const int* __restrict__ ei,
    const float* __restrict__ Wp1, const float* __restrict__ bp1,
    const float* __restrict__ Wp2, const float* __restrict__ bp2,
    const float* __restrict__ Wa1, const float* __restrict__ ba1,
    const float* __restrict__ Wa2, const float* __restrict__ ba2,
    int N, int E)
{
    extern __shared__ float sm[];
    float* sWp1 = sm;                 // [6][64]
    float* sWp2 = sWp1 + 384;         // [64][64]
    float* sWa1 = sWp2 + 4096;
    float* sWa2 = sWa1 + 4096;
    float* sbp1 = sWa2 + 4096;        // 64
    float* sbp2 = sbp1 + 64;
    float* sba1 = sbp2 + 64;
    float* sba2 = sba1 + 64;
    float* bufA = sba2 + 64;          // [64][RS]
    float* bufB = bufA + 64 * RS;     // [64][RS]
    float* sPos = bufB + 64 * RS;     // [64][8]
    int*   sSrc = (int*)(sPos + 64 * 8);  // 64
    int*   sDst = sSrc + 64;              // 64

    const int tid = threadIdx.x;
    for (int i = tid; i < 384;  i += 256) sWp1[i] = Wp1[i];
    for (int i = tid; i < 4096; i += 256) { sWp2[i] = Wp2[i]; sWa1[i] = Wa1[i]; sWa2[i] = Wa2[i]; }
    if (tid < 64) { sbp1[tid] = bp1[tid]; sbp2[tid] = bp2[tid]; sba1[tid] = ba1[tid]; sba2[tid] = ba2[tid]; }

    const int TOT = N + E;
    const int NT  = (TOT + 63) >> 6;
    const int r0 = (tid >> 3) * 2, c0 = (tid & 7) * 8;

    for (int tile = blockIdx.x; tile < NT; tile += gridDim.x) {
        const int base = tile << 6;
        __syncthreads();   // protect smem reuse across loop iterations

        // indices
        if (tid < 64) {
            int eid = base + tid;
            int s = 0, d = 0;
            if (eid < TOT) {
                if (eid < E) { s = ei[eid]; d = ei[E + eid]; }
                else         { s = d = eid - E; }
            }
            sSrc[tid] = s; sDst[tid] = d;
        }
        __syncthreads();

        // pos diffs
        for (int i = tid; i < 384; i += 256) {
            int r = i / 6, c = i - r * 6;
            sPos[r * 8 + c] = pos[sDst[r] * 6 + c] - pos[sSrc[r] * 6 + c];
        }
        __syncthreads();

        // hidden1 = relu(posdiff @ Wp1 + bp1)   (K=6, f32x2)
        {
            u64 acc[2][4];
            init_bias(sbp1, c0, acc);
#pragma unroll
            for (int k = 0; k < 6; k++) {
                const float* bp = sWp1 + k * 64 + c0;
                ulonglong2 bA = *(const ulonglong2*)(bp);
                ulonglong2 bB = *(const ulonglong2*)(bp + 4);
                u64 a0 = pack2s(sPos[(r0    ) * 8 + k]);
                u64 a1 = pack2s(sPos[(r0 + 1) * 8 + k]);
                acc[0][0] = ffma2(a0, bA.x, acc[0][0]);
                acc[0][1] = ffma2(a0, bA.y, acc[0][1]);
                acc[0][2] = ffma2(a0, bB.x, acc[0][2]);
                acc[0][3] = ffma2(a0, bB.y, acc[0][3]);
                acc[1][0] = ffma2(a1, bA.x, acc[1][0]);
                acc[1][1] = ffma2(a1, bA.y, acc[1][1]);
                acc[1][2] = ffma2(a1, bB.x, acc[1][2]);
                acc[1][3] = ffma2(a1, bB.y, acc[1][3]);
            }
            relu_store_smem(bufA, r0, c0, acc);
        }
        __syncthreads();

        // delta = relu(hidden1 @ Wp2 + bp2); y = a_dst[d]-a_src[s]+delta; tvd = v[s]+delta
        {
            u64 acc[2][4];
            init_bias(sbp2, c0, acc);
            gemm64_x2(bufA, sWp2, r0, c0, acc);
#pragma unroll
            for (int i = 0; i < 2; i++) {
                int r = r0 + i;
                int s = sSrc[r], d = sDst[r];
                float4 adA = *(const float4*)(g_adst + (size_t)d * 64 + c0);
                float4 adB = *(const float4*)(g_adst + (size_t)d * 64 + c0 + 4);
                float4 asA = *(const float4*)(g_asrc + (size_t)s * 64 + c0);
                float4 asB = *(const float4*)(g_asrc + (size_t)s * 64 + c0 + 4);
                float4 vvA = *(const float4*)(g_v    + (size_t)s * 64 + c0);
                float4 vvB = *(const float4*)(g_v    + (size_t)s * 64 + c0 + 4);
                float2 f0 = unpack2(acc[i][0]), f1 = unpack2(acc[i][1]);
                float2 f2 = unpack2(acc[i][2]), f3 = unpack2(acc[i][3]);
                float d0 = fmaxf(f0.x, 0.f), d1 = fmaxf(f0.y, 0.f);
                float d2 = fmaxf(f1.x, 0.f), d3 = fmaxf(f1.y, 0.f);
                float d4 = fmaxf(f2.x, 0.f), d5 = fmaxf(f2.y, 0.f);
                float d6 = fmaxf(f3.x, 0.f), d7 = fmaxf(f3.y, 0.f);
                float* bb = bufB + r * RS + c0;
                bb[0] = adA.x - asA.x + d0;  bb[1] = adA.y - asA.y + d1;
                bb[2] = adA.z - asA.z + d2;  bb[3] = adA.w - asA.w + d3;
                bb[4] = adB.x - asB.x + d4;  bb[5] = adB.y - asB.y + d5;
                bb[6] = adB.z - asB.z + d6;  bb[7] = adB.w - asB.w + d7;
                int eid = base + r;
                if (eid < TOT) {
                    *(float4*)(g_tvd + (size_t)eid * 64 + c0) =
                        make_float4(vvA.x + d0, vvA.y + d1, vvA.z + d2, vvA.w + d3);
                    *(float4*)(g_tvd + (size_t)eid * 64 + c0 + 4) =
                        make_float4(vvB.x + d4, vvB.y + d5, vvB.z + d6, vvB.w + d7);
                }
            }
        }
        __syncthreads();

        // hidden2 = relu(y @ Wa1 + ba1)
        {
            u64 acc[2][4];
            init_bias(sba1, c0, acc);
            gemm64_x2(bufB, sWa1, r0, c0, acc);
            relu_store_smem(bufA, r0, c0, acc);
        }
        __syncthreads();

        // alpha = relu(hidden2 @ Wa2 + ba2); e = exp(alpha); scatter
        {
            u64 acc[2][4];
            init_bias(sba2, c0, acc);
            gemm64_x2(bufA, sWa2, r0, c0, acc);
#pragma unroll
            for (int i = 0; i < 2; i++) {
                int r = r0 + i;
                int eid = base + r;
                if (eid < TOT) {
                    int d = sDst[r];
                    float e[8];
                    float2 f0 = unpack2(acc[i][0]), f1 = unpack2(acc[i][1]);
                    float2 f2 = unpack2(acc[i][2]), f3 = unpack2(acc[i][3]);
                    e[0] = __expf(fmaxf(f0.x, 0.f)); e[1] = __expf(fmaxf(f0.y, 0.f));
                    e[2] = __expf(fmaxf(f1.x, 0.f)); e[3] = __expf(fmaxf(f1.y, 0.f));
                    e[4] = __expf(fmaxf(f2.x, 0.f)); e[5] = __expf(fmaxf(f2.y, 0.f));
                    e[6] = __expf(fmaxf(f3.x, 0.f)); e[7] = __expf(fmaxf(f3.y, 0.f));
                    *(float4*)(g_eexp + (size_t)eid * 64 + c0)     = make_float4(e[0], e[1], e[2], e[3]);
                    *(float4*)(g_eexp + (size_t)eid * 64 + c0 + 4) = make_float4(e[4], e[5], e[6], e[7]);
#pragma unroll
                    for (int j = 0; j < 8; j++)
                        atomicAdd(&g_ssum[(size_t)d * 64 + c0 + j], e[j]);
                }
            }
        }
    }
}

// ---------------- K3: msg = eexp * tvd / s[dst]; scatter-sum to out_acc ----------------
__global__ void __launch_bounds__(256) k_edge2(const int* __restrict__ ei, int N, int E)
{
    int idx = blockIdx.x * 256 + threadIdx.x;
    const int TOT = N + E;
    if (idx >= TOT * 16) return;
    int eid = idx >> 4;
    int c0  = (idx & 15) << 2;
    int d = (eid < E) ? ei[E + eid] : (eid - E);
    float4 e4 = *(const float4*)(g_eexp + (size_t)eid * 64 + c0);
    float4 t4 = *(const float4*)(g_tvd  + (size_t)eid * 64 + c0);
    float4 s4 = *(const float4*)(g_ssum + (size_t)d * 64 + c0);
    atomicAdd(&g_oacc[d * 64 + c0 + 0], e4.x * t4.x / (s4.x + 1e-16f));
    atomicAdd(&g_oacc[d * 64 + c0 + 1], e4.y * t4.y / (s4.y + 1e-16f));
    atomicAdd(&g_oacc[d * 64 + c0 + 2], e4.z * t4.z / (s4.z + 1e-16f));
    atomicAdd(&g_oacc[d * 64 + c0 + 3], e4.w * t4.w / (s4.w + 1e-16f));
}

// ---------------- K4: out = relu(out_acc @ Wout + bout) + x ----------------
__global__ void __launch_bounds__(256) k_out(
    const float* __restrict__ x, const float* __restrict__ Wout,
    const float* __restrict__ bout, float* __restrict__ out, int N)
{
    extern __shared__ float sm[];
    float* sW = sm;
    float* sb = sW + 4096;
    float* As = sb + 64;  // [64][RS]
    const int tid = threadIdx.x;
    for (int i = tid; i < 4096; i += 256) sW[i] = Wout[i];
    if (tid < 64) sb[tid] = bout[tid];
    const int base = blockIdx.x * 64;
    for (int i = tid; i < 1024; i += 256) {
        int r = i >> 4, c4 = (i & 15) << 2;
        int row = base + r;
        float4 v = (row < N) ? *(const float4*)(g_oacc + (size_t)row * 64 + c4)
                             : make_float4(0.f, 0.f, 0.f, 0.f);
        *(float4*)(As + r * RS + c4) = v;
    }
    __syncthreads();
    const int r0 = (tid >> 3) * 2, c0 = (tid & 7) * 8;
    u64 acc[2][4];
    init_bias(sb, c0, acc);
    gemm64_x2(As, sW, r0, c0, acc);
#pragma unroll
    for (int i = 0; i < 2; i++) {
        int row = base + r0 + i;
        if (row < N) {
            float4 rA = *(const float4*)(x + (size_t)row * 64 + c0);
            float4 rB = *(const float4*)(x + (size_t)row * 64 + c0 + 4);
            float2 f0 = unpack2(acc[i][0]), f1 = unpack2(acc[i][1]);
            float2 f2 = unpack2(acc[i][2]), f3 = unpack2(acc[i][3]);
            *(float4*)(out + (size_t)row * 64 + c0) =
                make_float4(fmaxf(f0.x, 0.f) + rA.x, fmaxf(f0.y, 0.f) + rA.y,
                            fmaxf(f1.x, 0.f) + rA.z, fmaxf(f1.y, 0.f) + rA.w);
            *(float4*)(out + (size_t)row * 64 + c0 + 4) =
                make_float4(fmaxf(f2.x, 0.f) + rB.x, fmaxf(f2.y, 0.f) + rB.y,
                            fmaxf(f3.x, 0.f) + rB.z, fmaxf(f3.y, 0.f) + rB.w);
        }
    }
}

// ---------------- host ----------------
extern "C" void kernel_launch(void* const* d_in, const int* in_sizes, int n_in,
                              void* d_out, int out_size)
{
    const float* x    = (const float*)d_in[0];
    const float* pos  = (const float*)d_in[1];
    const int*   ei   = (const int*)  d_in[2];
    const float* Win  = (const float*)d_in[3];
    const float* bin  = (const float*)d_in[4];
    const float* Wout = (const float*)d_in[5];
    const float* bout = (const float*)d_in[6];
    const float* Wlin = (const float*)d_in[7];
    const float* Wsrc = (const float*)d_in[8];
    const float* Wdst = (const float*)d_in[9];
    const float* Wp1  = (const float*)d_in[10];
    const float* bp1  = (const float*)d_in[11];
    const float* Wp2  = (const float*)d_in[12];
    const float* bp2  = (const float*)d_in[13];
    const float* Wa1  = (const float*)d_in[14];
    const float* ba1  = (const float*)d_in[15];
    const float* Wa2  = (const float*)d_in[16];
    const float* ba2  = (const float*)d_in[17];

    const int N = in_sizes[0] / 64;
    const int E = in_sizes[2] / 2;
    const int TOT = N + E;

    void *p_ssum, *p_oacc;
    cudaGetSymbolAddress(&p_ssum, g_ssum);
    cudaGetSymbolAddress(&p_oacc, g_oacc);
    cudaMemsetAsync(p_ssum, 0, (size_t)N * 64 * sizeof(float), 0);
    cudaMemsetAsync(p_oacc, 0, (size_t)N * 64 * sizeof(float), 0);

    const int smem_proj  = (4 * 4096 + 64 + 2 * 64 * RS) * 4;
    const int smem_edge1 = (384 + 3 * 4096 + 4 * 64 + 2 * 64 * RS + 64 * 8) * 4 + 128 * 4;
    const int smem_out   = (4096 + 64 + 64 * RS) * 4;

    cudaFuncSetAttribute(k_proj,  cudaFuncAttributeMaxDynamicSharedMemorySize, smem_proj);
    cudaFuncSetAttribute(k_edge1, cudaFuncAttributeMaxDynamicSharedMemorySize, smem_edge1);

    const int ntile_n = (N + 63) / 64;
    k_proj<<<ntile_n, 256, smem_proj>>>(x, Win, bin, Wsrc, Wdst, Wlin, N);
    k_edge1<<<296, 256, smem_edge1>>>(pos, ei, Wp1, bp1, Wp2, bp2, Wa1, ba1, Wa2, ba2, N, E);
    k_edge2<<<(TOT * 16 + 255) / 256, 256>>>(ei, N, E);
    k_out<<<ntile_n, 256, smem_out>>>(x, Wout, bout, (float*)d_out, N);
}

// round 4
// speedup vs baseline: 2.2540x; 2.2540x over previous
#include <cuda_runtime.h>
#include <math.h>

#define F 64
#define N_CAP   50176
#define RS 68            // smem row stride (floats): 272B keeps float4 rows 16B-aligned

// ---------------- device scratch (static globals; no runtime alloc) ----------------
__device__ float g_asrc[N_CAP * F];
__device__ float g_adst[N_CAP * F];
__device__ float g_v   [N_CAP * F];
__device__ float g_ssum[N_CAP * F];   // sum of exp(alpha) per dst
__device__ float g_num [N_CAP * F];   // sum of exp(alpha)*(v[src]+delta) per dst

// ---------------- 4x4 register-tiled 64x64x64 smem GEMM (accumulating) ----------------
__device__ __forceinline__ void gemm64_acc(const float* __restrict__ As,  // [64][RS]
                                           const float* __restrict__ Bs,  // [64][64]
                                           int r0, int c0, float acc[4][4])
{
#pragma unroll 4
    for (int k = 0; k < 64; k++) {
        float4 b = *(const float4*)(Bs + k * 64 + c0);
        float a0 = As[(r0 + 0) * RS + k];
        float a1 = As[(r0 + 1) * RS + k];
        float a2 = As[(r0 + 2) * RS + k];
        float a3 = As[(r0 + 3) * RS + k];
        acc[0][0] += a0 * b.x; acc[0][1] += a0 * b.y; acc[0][2] += a0 * b.z; acc[0][3] += a0 * b.w;
        acc[1][0] += a1 * b.x; acc[1][1] += a1 * b.y; acc[1][2] += a1 * b.z; acc[1][3] += a1 * b.w;
        acc[2][0] += a2 * b.x; acc[2][1] += a2 * b.y; acc[2][2] += a2 * b.z; acc[2][3] += a2 * b.w;
        acc[3][0] += a3 * b.x; acc[3][1] += a3 * b.y; acc[3][2] += a3 * b.z; acc[3][3] += a3 * b.w;
    }
}

// ---------------- K1: h = relu(x@Win+b); a_src=h@Wsrc; a_dst=h@Wdst; v=h@Wlin ----------------
__global__ void __launch_bounds__(256) k_proj(
    const float* __restrict__ x,
    const float* __restrict__ Win, const float* __restrict__ bin,
    const float* __restrict__ Wsrc, const float* __restrict__ Wdst,
    const float* __restrict__ Wlin, int N)
{
    extern __shared__ float sm[];
    float* sWin = sm;
    float* sWs  = sWin + 4096;
    float* sWd  = sWs  + 4096;
    float* sWl  = sWd  + 4096;
    float* sb   = sWl  + 4096;
    float* xs   = sb + 64;          // [64][RS]
    float* hs   = xs + 64 * RS;     // [64][RS]
    const int tid = threadIdx.x;

    for (int i = tid; i < 4096; i += 256) {
        sWin[i] = Win[i]; sWs[i] = Wsrc[i]; sWd[i] = Wdst[i]; sWl[i] = Wlin[i];
    }
    if (tid < 64) sb[tid] = bin[tid];

    const int base = blockIdx.x * 64;
    for (int i = tid; i < 1024; i += 256) {
        int r = i >> 4, c4 = (i & 15) << 2;
        int row = base + r;
        float4 v = (row < N) ? *(const float4*)(x + (size_t)row * 64 + c4)
                             : make_float4(0.f, 0.f, 0.f, 0.f);
        *(float4*)(xs + r * RS + c4) = v;
    }
    __syncthreads();

    const int tr = tid >> 4, tc = tid & 15, r0 = tr * 4, c0 = tc * 4;
    float acc[4][4];

    // h
#pragma unroll
    for (int i = 0; i < 4; i++)
#pragma unroll
        for (int j = 0; j < 4; j++) acc[i][j] = sb[c0 + j];
    gemm64_acc(xs, sWin, r0, c0, acc);
#pragma unroll
    for (int i = 0; i < 4; i++)
#pragma unroll
        for (int j = 0; j < 4; j++) hs[(r0 + i) * RS + c0 + j] = fmaxf(acc[i][j], 0.f);
    __syncthreads();

    // a_src
#pragma unroll
    for (int i = 0; i < 4; i++)
#pragma unroll
        for (int j = 0; j < 4; j++) acc[i][j] = 0.f;
    gemm64_acc(hs, sWs, r0, c0, acc);
#pragma unroll
    for (int i = 0; i < 4; i++) {
        int row = base + r0 + i;
        if (row < N) *(float4*)(g_asrc + (size_t)row * 64 + c0) =
            make_float4(acc[i][0], acc[i][1], acc[i][2], acc[i][3]);
    }

    // a_dst
#pragma unroll
    for (int i = 0; i < 4; i++)
#pragma unroll
        for (int j = 0; j < 4; j++) acc[i][j] = 0.f;
    gemm64_acc(hs, sWd, r0, c0, acc);
#pragma unroll
    for (int i = 0; i < 4; i++) {
        int row = base + r0 + i;
        if (row < N) *(float4*)(g_adst + (size_t)row * 64 + c0) =
            make_float4(acc[i][0], acc[i][1], acc[i][2], acc[i][3]);
    }

    // v
#pragma unroll
    for (int i = 0; i < 4; i++)
#pragma unroll
        for (int j = 0; j < 4; j++) acc[i][j] = 0.f;
    gemm64_acc(hs, sWl, r0, c0, acc);
#pragma unroll
    for (int i = 0; i < 4; i++) {
        int row = base + r0 + i;
        if (row < N) *(float4*)(g_v + (size_t)row * 64 + c0) =
            make_float4(acc[i][0], acc[i][1], acc[i][2], acc[i][3]);
    }
}

// ---------------- K2: per-edge MLPs; accumulate e and e*(v[src]+delta) ----------------
__global__ void __launch_bounds__(256, 2) k_edge1(
    const float* __restrict__ pos, const int* __restrict__ ei,
    const float* __restrict__ Wp1, const float* __restrict__ bp1,
    const float* __restrict__ Wp2, const float* __restrict__ bp2,
    const float* __restrict__ Wa1, const float* __restrict__ ba1,
    const float* __restrict__ Wa2, const float* __restrict__ ba2,
    int N, int E)
{
    extern __shared__ float sm[];
    float* sWp1 = sm;                 // [6][64]
    float* sWp2 = sWp1 + 384;         // [64][64]
    float* sWa1 = sWp2 + 4096;
    float* sWa2 = sWa1 + 4096;
    float* sbp1 = sWa2 + 4096;        // 64
    float* sbp2 = sbp1 + 64;
    float* sba1 = sbp2 + 64;
    float* sba2 = sba1 + 64;
    float* bufA = sba2 + 64;          // [64][RS]
    float* bufB = bufA + 64 * RS;     // [64][RS]
    float* sPos = bufB + 64 * RS;     // [64][8]
    int*   sSrc = (int*)(sPos + 64 * 8);  // 64
    int*   sDst = sSrc + 64;              // 64

    const int tid = threadIdx.x;
    for (int i = tid; i < 384;  i += 256) sWp1[i] = Wp1[i];
    for (int i = tid; i < 4096; i += 256) { sWp2[i] = Wp2[i]; sWa1[i] = Wa1[i]; sWa2[i] = Wa2[i]; }
    if (tid < 64) { sbp1[tid] = bp1[tid]; sbp2[tid] = bp2[tid]; sba1[tid] = ba1[tid]; sba2[tid] = ba2[tid]; }

    const int TOT = N + E;
    const int NT  = (TOT + 63) >> 6;
    const int tr = tid >> 4, tc = tid & 15, r0 = tr * 4, c0 = tc * 4;

    for (int tile = blockIdx.x; tile < NT; tile += gridDim.x) {
        const int base = tile << 6;
        __syncthreads();   // protect smem reuse across loop iterations

        // indices
        if (tid < 64) {
            int eid = base + tid;
            int s = 0, d = 0;
            if (eid < TOT) {
                if (eid < E) { s = ei[eid]; d = ei[E + eid]; }
                else         { s = d = eid - E; }
            }
            sSrc[tid] = s; sDst[tid] = d;
        }
        __syncthreads();

        // pos diffs
        for (int i = tid; i < 384; i += 256) {
            int r = i / 6, c = i - r * 6;
            sPos[r * 8 + c] = pos[sDst[r] * 6 + c] - pos[sSrc[r] * 6 + c];
        }
        __syncthreads();

        // hidden1 = relu(posdiff @ Wp1 + bp1)   (K=6)
        for (int i = tid; i < 4096; i += 256) {
            int r = i >> 6, c = i & 63;
            float a = sbp1[c];
#pragma unroll
            for (int k = 0; k < 6; k++) a += sPos[r * 8 + k] * sWp1[k * 64 + c];
            bufA[r * RS + c] = fmaxf(a, 0.f);
        }
        __syncthreads();

        // delta = relu(hidden1 @ Wp2 + bp2); y = a_dst[d]-a_src[s]+delta (smem);
        // tvd = v[s]+delta kept in registers (same thread reuses it in the alpha stage)
        float tvd[4][4];
        float acc[4][4];
#pragma unroll
        for (int i = 0; i < 4; i++)
#pragma unroll
            for (int j = 0; j < 4; j++) acc[i][j] = sbp2[c0 + j];
        gemm64_acc(bufA, sWp2, r0, c0, acc);
#pragma unroll
        for (int i = 0; i < 4; i++) {
            int r = r0 + i;
            int s = sSrc[r], d = sDst[r];
            float4 ad = *(const float4*)(g_adst + (size_t)d * 64 + c0);
            float4 as = *(const float4*)(g_asrc + (size_t)s * 64 + c0);
            float4 vv = *(const float4*)(g_v    + (size_t)s * 64 + c0);
            float d0 = fmaxf(acc[i][0], 0.f), d1 = fmaxf(acc[i][1], 0.f);
            float d2 = fmaxf(acc[i][2], 0.f), d3 = fmaxf(acc[i][3], 0.f);
            bufB[r * RS + c0 + 0] = ad.x - as.x + d0;
            bufB[r * RS + c0 + 1] = ad.y - as.y + d1;
            bufB[r * RS + c0 + 2] = ad.z - as.z + d2;
            bufB[r * RS + c0 + 3] = ad.w - as.w + d3;
            tvd[i][0] = vv.x + d0; tvd[i][1] = vv.y + d1;
            tvd[i][2] = vv.z + d2; tvd[i][3] = vv.w + d3;
        }
        __syncthreads();

        // hidden2 = relu(y @ Wa1 + ba1)
#pragma unroll
        for (int i = 0; i < 4; i++)
#pragma unroll
            for (int j = 0; j < 4; j++) acc[i][j] = sba1[c0 + j];
        gemm64_acc(bufB, sWa1, r0, c0, acc);
#pragma unroll
        for (int i = 0; i < 4; i++)
#pragma unroll
            for (int j = 0; j < 4; j++) bufA[(r0 + i) * RS + c0 + j] = fmaxf(acc[i][j], 0.f);
        __syncthreads();

        // alpha = relu(hidden2 @ Wa2 + ba2); e = exp(alpha);
        // accumulate g_ssum[d] += e and g_num[d] += e * tvd
#pragma unroll
        for (int i = 0; i < 4; i++)
#pragma unroll
            for (int j = 0; j < 4; j++) acc[i][j] = sba2[c0 + j];
        gemm64_acc(bufA, sWa2, r0, c0, acc);
#pragma unroll
        for (int i = 0; i < 4; i++) {
            int r = r0 + i;
            int eid = base + r;
            if (eid < TOT) {
                int d = sDst[r];
                float* ps = g_ssum + (size_t)d * 64 + c0;
                float* pn = g_num  + (size_t)d * 64 + c0;
#pragma unroll
                for (int j = 0; j < 4; j++) {
                    float e = __expf(fmaxf(acc[i][j], 0.f));
                    atomicAdd(ps + j, e);
                    atomicAdd(pn + j, e * tvd[i][j]);
                }
            }
        }
    }
}

// ---------------- K3: out = relu((num/ssum) @ Wout + bout) + x ----------------
__global__ void __launch_bounds__(256) k_out(
    const float* __restrict__ x, const float* __restrict__ Wout,
    const float* __restrict__ bout, float* __restrict__ out, int N)
{
    extern __shared__ float sm[];
    float* sW = sm;
    float* sb = sW + 4096;
    float* As = sb + 64;  // [64][RS]
    const int tid = threadIdx.x;
    for (int i = tid; i < 4096; i += 256) sW[i] = Wout[i];
    if (tid < 64) sb[tid] = bout[tid];
    const int base = blockIdx.x * 64;
    for (int i = tid; i < 1024; i += 256) {
        int r = i >> 4, c4 = (i & 15) << 2;
        int row = base + r;
        float4 v = make_float4(0.f, 0.f, 0.f, 0.f);
        if (row < N) {
            float4 n4 = *(const float4*)(g_num  + (size_t)row * 64 + c4);
            float4 s4 = *(const float4*)(g_ssum + (size_t)row * 64 + c4);
            v = make_float4(n4.x / (s4.x + 1e-16f), n4.y / (s4.y + 1e-16f),
                            n4.z / (s4.z + 1e-16f), n4.w / (s4.w + 1e-16f));
        }
        *(float4*)(As + r * RS + c4) = v;
    }
    __syncthreads();
    const int tr = tid >> 4, tc = tid & 15, r0 = tr * 4, c0 = tc * 4;
    float acc[4][4];
#pragma unroll
    for (int i = 0; i < 4; i++)
#pragma unroll
        for (int j = 0; j < 4; j++) acc[i][j] = sb[c0 + j];
    gemm64_acc(As, sW, r0, c0, acc);
#pragma unroll
    for (int i = 0; i < 4; i++) {
        int row = base + r0 + i;
        if (row < N) {
            float4 res = *(const float4*)(x + (size_t)row * 64 + c0);
            *(float4*)(out + (size_t)row * 64 + c0) =
                make_float4(fmaxf(acc[i][0], 0.f) + res.x,
                            fmaxf(acc[i][1], 0.f) + res.y,
                            fmaxf(acc[i][2], 0.f) + res.z,
                            fmaxf(acc[i][3], 0.f) + res.w);
        }
    }
}

// ---------------- host ----------------
extern "C" void kernel_launch(void* const* d_in, const int* in_sizes, int n_in,
                              void* d_out, int out_size)
{
    const float* x    = (const float*)d_in[0];
    const float* pos  = (const float*)d_in[1];
    const int*   ei   = (const int*)  d_in[2];
    const float* Win  = (const float*)d_in[3];
    const float* bin  = (const float*)d_in[4];
    const float* Wout = (const float*)d_in[5];
    const float* bout = (const float*)d_in[6];
    const float* Wlin = (const float*)d_in[7];
    const float* Wsrc = (const float*)d_in[8];
    const float* Wdst = (const float*)d_in[9];
    const float* Wp1  = (const float*)d_in[10];
    const float* bp1  = (const float*)d_in[11];
    const float* Wp2  = (const float*)d_in[12];
    const float* bp2  = (const float*)d_in[13];
    const float* Wa1  = (const float*)d_in[14];
    const float* ba1  = (const float*)d_in[15];
    const float* Wa2  = (const float*)d_in[16];
    const float* ba2  = (const float*)d_in[17];

    const int N = in_sizes[0] / 64;
    const int E = in_sizes[2] / 2;

    void *p_ssum, *p_num;
    cudaGetSymbolAddress(&p_ssum, g_ssum);
    cudaGetSymbolAddress(&p_num,  g_num);
    cudaMemsetAsync(p_ssum, 0, (size_t)N * 64 * sizeof(float), 0);
    cudaMemsetAsync(p_num,  0, (size_t)N * 64 * sizeof(float), 0);

    const int smem_proj  = (4 * 4096 + 64 + 2 * 64 * RS) * 4;
    const int smem_edge1 = (384 + 3 * 4096 + 4 * 64 + 2 * 64 * RS + 64 * 8) * 4 + 128 * 4;
    const int smem_out   = (4096 + 64 + 64 * RS) * 4;

    cudaFuncSetAttribute(k_proj,  cudaFuncAttributeMaxDynamicSharedMemorySize, smem_proj);
    cudaFuncSetAttribute(k_edge1, cudaFuncAttributeMaxDynamicSharedMemorySize, smem_edge1);

    const int ntile_n = (N + 63) / 64;
    k_proj<<<ntile_n, 256, smem_proj>>>(x, Win, bin, Wsrc, Wdst, Wlin, N);
    k_edge1<<<296, 256, smem_edge1>>>(pos, ei, Wp1, bp1, Wp2, bp2, Wa1, ba1, Wa2, ba2, N, E);
    k_out<<<ntile_n, 256, smem_out>>>(x, Wout, bout, (float*)d_out, N);
}

// round 6
// speedup vs baseline: 4.3762x; 1.9415x over previous
#include <cuda_runtime.h>
#include <cuda_bf16.h>
#include <stdint.h>
#include <math.h>

#define F 64
#define N_CAP 50176
#define RS 68            // smem row stride (floats) for k_proj/k_out

// ---------------- device scratch ----------------
__device__ float g_asrc[N_CAP * F];
__device__ float g_adst[N_CAP * F];
__device__ float g_v   [N_CAP * F];
__device__ float g_ssum[N_CAP * F];   // sum of exp(alpha) per dst
__device__ float g_num [N_CAP * F];   // sum of exp(alpha)*(v[src]+delta) per dst

// ---------------- mma.sync / ldmatrix helpers (sm_80+ baseline features) ----------------
__device__ __forceinline__ void ldsm4(uint32_t r[4], uint32_t addr) {
    asm volatile("ldmatrix.sync.aligned.m8n8.x4.shared.b16 {%0,%1,%2,%3}, [%4];"
                 : "=r"(r[0]), "=r"(r[1]), "=r"(r[2]), "=r"(r[3]) : "r"(addr));
}
__device__ __forceinline__ void ldsm4t(uint32_t r[4], uint32_t addr) {
    asm volatile("ldmatrix.sync.aligned.m8n8.x4.trans.shared.b16 {%0,%1,%2,%3}, [%4];"
                 : "=r"(r[0]), "=r"(r[1]), "=r"(r[2]), "=r"(r[3]) : "r"(addr));
}
__device__ __forceinline__ void mma16816(float d[4], const uint32_t a[4], uint32_t b0, uint32_t b1) {
    asm volatile("mma.sync.aligned.m16n8k16.row.col.f32.bf16.bf16.f32 "
                 "{%0,%1,%2,%3}, {%4,%5,%6,%7}, {%8,%9}, {%0,%1,%2,%3};"
                 : "+f"(d[0]), "+f"(d[1]), "+f"(d[2]), "+f"(d[3])
                 : "r"(a[0]), "r"(a[1]), "r"(a[2]), "r"(a[3]), "r"(b0), "r"(b1));
}
__device__ __forceinline__ uint32_t smem_u32(const void* p) {
    uint32_t a;
    asm("{ .reg .u64 t; cvta.to.shared.u64 t, %1; cvt.u32.u64 %0, t; }" : "=r"(a) : "l"(p));
    return a;
}
__device__ __forceinline__ void red4(float* p, float a, float b, float c, float d) {
    asm volatile("red.relaxed.gpu.global.add.v4.f32 [%0], {%1, %2, %3, %4};"
                 :: "l"(p), "f"(a), "f"(b), "f"(c), "f"(d) : "memory");
}
// split fp32 -> bf16 hi (at off) + lo (at off+128)
__device__ __forceinline__ void split1(char* base, uint32_t off, float w) {
    __nv_bfloat16 h = __float2bfloat16(w);
    __nv_bfloat16 l = __float2bfloat16(w - __bfloat162float(h));
    *(__nv_bfloat16*)(base + off) = h;
    *(__nv_bfloat16*)(base + off + 128) = l;
}
__device__ __forceinline__ void split2(char* base, uint32_t off, float a, float b) {
    __nv_bfloat162 h = __float22bfloat162_rn(make_float2(a, b));
    float2 hf = __bfloat1622float2(h);
    __nv_bfloat162 l = __float22bfloat162_rn(make_float2(a - hf.x, b - hf.y));
    *(__nv_bfloat162*)(base + off) = h;
    *(__nv_bfloat162*)(base + off + 128) = l;
}

// ---------------- k_edge_tc smem layout (bytes) ----------------
// A / B rows: [hi 128B][lo 128B][pad 16B] = 272B stride (272 mod 128 = 16 -> conflict-free ldmatrix)
#define OFF_BP1 0
#define OFF_BP2 256
#define OFF_BA1 512
#define OFF_BA2 768
#define OFF_WP1 1024            // [6][64] fp32 = 1536
#define OFF_A   2560            // 128 rows * 272
#define OFF_B0  37376           // Wp2 (n-permuted): 64*272 = 17408
#define OFF_B1  54784           // Wa1
#define OFF_B2  72192           // Wa2 (n-permuted)
#define SMEM_EDGE 89600

// one 64x64x64 GEMM stage: acc[8][4] += A(16x64,hi+lo) @ B(64x64,hi+lo)
__device__ __forceinline__ void stage_mma(uint32_t aBase, uint32_t bBase,
                                          uint32_t lrow272, uint32_t lcolb, float acc[8][4])
{
#pragma unroll
    for (int kk = 0; kk < 64; kk += 16) {
        uint32_t aH[4], aL[4];
        uint32_t aaddr = aBase + lrow272 + kk * 2 + lcolb;
        ldsm4(aH, aaddr);
        ldsm4(aL, aaddr + 128);
#pragma unroll
        for (int np = 0; np < 4; np++) {            // n0 = 16*np
            uint32_t bH[4], bL[4];
            uint32_t baddr = bBase + kk * 272 + lrow272 + np * 32 + lcolb;
            ldsm4t(bH, baddr);
            ldsm4t(bL, baddr + 128);
            mma16816(acc[2 * np], aH, bH[0], bH[1]);
            mma16816(acc[2 * np], aH, bL[0], bL[1]);
            mma16816(acc[2 * np], aL, bH[0], bH[1]);
            mma16816(acc[2 * np], aL, bL[0], bL[1]);
            mma16816(acc[2 * np + 1], aH, bH[2], bH[3]);
            mma16816(acc[2 * np + 1], aH, bL[2], bL[3]);
            mma16816(acc[2 * np + 1], aL, bH[2], bH[3]);
            mma16816(acc[2 * np + 1], aL, bL[2], bL[3]);
        }
    }
}

// ============================================================================
// K2: per-edge MLPs on tensor cores; accumulate e and e*(v[src]+delta)
// ============================================================================
__global__ void __launch_bounds__(256, 2) k_edge_tc(
    const float* __restrict__ pos, const int* __restrict__ ei,
    const float* __restrict__ Wp1, const float* __restrict__ bp1,
    const float* __restrict__ Wp2, const float* __restrict__ bp2,
    const float* __restrict__ Wa1, const float* __restrict__ ba1,
    const float* __restrict__ Wa2, const float* __restrict__ ba2,
    int N, int E)
{
    extern __shared__ char smem[];
    const uint32_t sb = smem_u32(smem);
    const int tid  = threadIdx.x;
    const int wid  = tid >> 5;
    const int lane = tid & 31;
    const int wb   = wid * 16;           // warp's row stripe in the 128-row tile
    const int g    = lane >> 2;          // fragment group (row)
    const int tig  = lane & 3;           // thread-in-group (col pair)

    float* sbp1 = (float*)(smem + OFF_BP1);
    float* sbp2 = (float*)(smem + OFF_BP2);
    float* sba1 = (float*)(smem + OFF_BA1);
    float* sba2 = (float*)(smem + OFF_BA2);
    float* sWp1 = (float*)(smem + OFF_WP1);

    if (tid < 64) { sbp1[tid] = bp1[tid]; sbp2[tid] = bp2[tid]; sba1[tid] = ba1[tid]; sba2[tid] = ba2[tid]; }
    for (int i = tid; i < 384; i += 256) sWp1[i] = Wp1[i];
    // stage weights: B[k][p] bf16-split; Wp2/Wa2 n-permuted so fragment cols are
    // 16 consecutive logical features per lane: L(p) = 16*((p>>1)&3) + 2*(p>>3) + (p&1)
    for (int idx = tid; idx < 4096; idx += 256) {
        int k = idx >> 6, p = idx & 63;
        int Lp = 16 * ((p >> 1) & 3) + 2 * (p >> 3) + (p & 1);
        uint32_t off = (uint32_t)k * 272 + (uint32_t)p * 2;
        split1(smem + OFF_B0, off, Wp2[k * 64 + Lp]);
        split1(smem + OFF_B1, off, Wa1[k * 64 + p]);
        split1(smem + OFF_B2, off, Wa2[k * 64 + Lp]);
    }
    __syncthreads();

    const int TOT = N + E;
    const int NT  = (TOT + 127) >> 7;
    const uint32_t lrow272 = (uint32_t)((lane & 7) + 8 * ((lane >> 3) & 1)) * 272;
    const uint32_t lcolb   = (uint32_t)((lane >> 4) & 1) * 16;
    const uint32_t aBase   = sb + OFF_A + (uint32_t)wb * 272;
    char* smA = smem + OFF_A;

    for (int tile = blockIdx.x; tile < NT; tile += gridDim.x) {
        const int tbase = tile << 7;

        // ---- hidden1 = relu(posdiff @ Wp1 + bp1) -> A (warp-local rows) ----
        {
            int rh = wb + (lane >> 1);
            int eidh = tbase + rh;
            int sh = 0, dh = 0;
            if (eidh < TOT) {
                if (eidh < E) { sh = ei[eidh]; dh = ei[E + eidh]; }
                else          { sh = dh = eidh - E; }
            }
            float p6[6];
#pragma unroll
            for (int k = 0; k < 6; k++) p6[k] = pos[dh * 6 + k] - pos[sh * 6 + k];
            const int cbase = 32 * (lane & 1);
            const uint32_t rowb = (uint32_t)rh * 272;
#pragma unroll
            for (int cc = 0; cc < 32; cc += 2) {
                int c = cbase + cc;
                float h0 = sbp1[c], h1 = sbp1[c + 1];
#pragma unroll
                for (int k = 0; k < 6; k++) {
                    h0 = fmaf(p6[k], sWp1[k * 64 + c], h0);
                    h1 = fmaf(p6[k], sWp1[k * 64 + c + 1], h1);
                }
                split2(smA, rowb + c * 2, fmaxf(h0, 0.f), fmaxf(h1, 0.f));
            }
        }
        __syncwarp();

        // fragment-row bookkeeping
        const int er1 = wb + g, er2 = er1 + 8;
        const int eid1 = tbase + er1, eid2 = tbase + er2;
        int s1 = 0, d1 = 0, s2 = 0, d2 = 0;
        if (eid1 < TOT) { if (eid1 < E) { s1 = ei[eid1]; d1 = ei[E + eid1]; } else s1 = d1 = eid1 - E; }
        if (eid2 < TOT) { if (eid2 < E) { s2 = ei[eid2]; d2 = ei[E + eid2]; } else s2 = d2 = eid2 - E; }

        float acc[8][4];
#pragma unroll
        for (int i = 0; i < 8; i++)
#pragma unroll
            for (int j = 0; j < 4; j++) acc[i][j] = 0.f;

        // ---- stage 1: delta = relu(hidden1 @ Wp2 + bp2)  (n-permuted) ----
        stage_mma(aBase, sb + OFF_B0, lrow272, lcolb, acc);
        __syncwarp();

        float tvd1[16], tvd2[16];
        {
            const uint32_t rowb1 = (uint32_t)er1 * 272, rowb2 = (uint32_t)er2 * 272;
#pragma unroll
            for (int q = 0; q < 4; q++) {
                const int c = 16 * tig + 4 * q;
                // row er1
                {
                    float4 ad = *(const float4*)(g_adst + (size_t)d1 * 64 + c);
                    float4 as = *(const float4*)(g_asrc + (size_t)s1 * 64 + c);
                    float4 vv = *(const float4*)(g_v    + (size_t)s1 * 64 + c);
                    float e0 = fmaxf(acc[2 * q][0] + sbp2[c + 0], 0.f);
                    float e1 = fmaxf(acc[2 * q][1] + sbp2[c + 1], 0.f);
                    float e2 = fmaxf(acc[2 * q + 1][0] + sbp2[c + 2], 0.f);
                    float e3 = fmaxf(acc[2 * q + 1][1] + sbp2[c + 3], 0.f);
                    split2(smA, rowb1 + c * 2,     ad.x - as.x + e0, ad.y - as.y + e1);
                    split2(smA, rowb1 + c * 2 + 4, ad.z - as.z + e2, ad.w - as.w + e3);
                    tvd1[4 * q + 0] = vv.x + e0; tvd1[4 * q + 1] = vv.y + e1;
                    tvd1[4 * q + 2] = vv.z + e2; tvd1[4 * q + 3] = vv.w + e3;
                }
                // row er2
                {
                    float4 ad = *(const float4*)(g_adst + (size_t)d2 * 64 + c);
                    float4 as = *(const float4*)(g_asrc + (size_t)s2 * 64 + c);
                    float4 vv = *(const float4*)(g_v    + (size_t)s2 * 64 + c);
                    float e0 = fmaxf(acc[2 * q][2] + sbp2[c + 0], 0.f);
                    float e1 = fmaxf(acc[2 * q][3] + sbp2[c + 1], 0.f);
                    float e2 = fmaxf(acc[2 * q + 1][2] + sbp2[c + 2], 0.f);
                    float e3 = fmaxf(acc[2 * q + 1][3] + sbp2[c + 3], 0.f);
                    split2(smA, rowb2 + c * 2,     ad.x - as.x + e0, ad.y - as.y + e1);
                    split2(smA, rowb2 + c * 2 + 4, ad.z - as.z + e2, ad.w - as.w + e3);
                    tvd2[4 * q + 0] = vv.x + e0; tvd2[4 * q + 1] = vv.y + e1;
                    tvd2[4 * q + 2] = vv.z + e2; tvd2[4 * q + 3] = vv.w + e3;
                }
            }
        }
        __syncwarp();

        // ---- stage 2: hidden2 = relu(y @ Wa1 + ba1)  (identity n) ----
#pragma unroll
        for (int i = 0; i < 8; i++)
#pragma unroll
            for (int j = 0; j < 4; j++) acc[i][j] = 0.f;
        stage_mma(aBase, sb + OFF_B1, lrow272, lcolb, acc);
        __syncwarp();
        {
            const uint32_t rowb1 = (uint32_t)er1 * 272, rowb2 = (uint32_t)er2 * 272;
#pragma unroll
            for (int nt = 0; nt < 8; nt++) {
                const int c = 8 * nt + 2 * tig;
                split2(smA, rowb1 + c * 2, fmaxf(acc[nt][0] + sba1[c], 0.f),
                                           fmaxf(acc[nt][1] + sba1[c + 1], 0.f));
                split2(smA, rowb2 + c * 2, fmaxf(acc[nt][2] + sba1[c], 0.f),
                                           fmaxf(acc[nt][3] + sba1[c + 1], 0.f));
            }
        }
        __syncwarp();

        // ---- stage 3: alpha = relu(hidden2 @ Wa2 + ba2) (n-permuted); e=exp; scatter ----
#pragma unroll
        for (int i = 0; i < 8; i++)
#pragma unroll
            for (int j = 0; j < 4; j++) acc[i][j] = 0.f;
        stage_mma(aBase, sb + OFF_B2, lrow272, lcolb, acc);
        __syncwarp();
#pragma unroll
        for (int q = 0; q < 4; q++) {
            const int c = 16 * tig + 4 * q;
            if (eid1 < TOT) {
                float e0 = __expf(fmaxf(acc[2 * q][0] + sba2[c + 0], 0.f));
                float e1 = __expf(fmaxf(acc[2 * q][1] + sba2[c + 1], 0.f));
                float e2 = __expf(fmaxf(acc[2 * q + 1][0] + sba2[c + 2], 0.f));
                float e3 = __expf(fmaxf(acc[2 * q + 1][1] + sba2[c + 3], 0.f));
                red4(g_ssum + (size_t)d1 * 64 + c, e0, e1, e2, e3);
                red4(g_num  + (size_t)d1 * 64 + c, e0 * tvd1[4 * q + 0], e1 * tvd1[4 * q + 1],
                                                   e2 * tvd1[4 * q + 2], e3 * tvd1[4 * q + 3]);
            }
            if (eid2 < TOT) {
                float e0 = __expf(fmaxf(acc[2 * q][2] + sba2[c + 0], 0.f));
                float e1 = __expf(fmaxf(acc[2 * q][3] + sba2[c + 1], 0.f));
                float e2 = __expf(fmaxf(acc[2 * q + 1][2] + sba2[c + 2], 0.f));
                float e3 = __expf(fmaxf(acc[2 * q + 1][3] + sba2[c + 3], 0.f));
                red4(g_ssum + (size_t)d2 * 64 + c, e0, e1, e2, e3);
                red4(g_num  + (size_t)d2 * 64 + c, e0 * tvd2[4 * q + 0], e1 * tvd2[4 * q + 1],
                                                   e2 * tvd2[4 * q + 2], e3 * tvd2[4 * q + 3]);
            }
        }
        __syncwarp();
    }
}

// ============================================================================
// K1 / K3: node GEMMs (unchanged from R4-proven versions)
// ============================================================================
__device__ __forceinline__ void gemm64_acc(const float* __restrict__ As,
                                           const float* __restrict__ Bs,
                                           int r0, int c0, float acc[4][4])
{
#pragma unroll 4
    for (int k = 0; k < 64; k++) {
        float4 b = *(const float4*)(Bs + k * 64 + c0);
        float a0 = As[(r0 + 0) * RS + k];
        float a1 = As[(r0 + 1) * RS + k];
        float a2 = As[(r0 + 2) * RS + k];
        float a3 = As[(r0 + 3) * RS + k];
        acc[0][0] += a0 * b.x; acc[0][1] += a0 * b.y; acc[0][2] += a0 * b.z; acc[0][3] += a0 * b.w;
        acc[1][0] += a1 * b.x; acc[1][1] += a1 * b.y; acc[1][2] += a1 * b.z; acc[1][3] += a1 * b.w;
        acc[2][0] += a2 * b.x; acc[2][1] += a2 * b.y; acc[2][2] += a2 * b.z; acc[2][3] += a2 * b.w;
        acc[3][0] += a3 * b.x; acc[3][1] += a3 * b.y; acc[3][2] += a3 * b.z; acc[3][3] += a3 * b.w;
    }
}

__global__ void __launch_bounds__(256) k_proj(
    const float* __restrict__ x,
    const float* __restrict__ Win, const float* __restrict__ bin,
    const float* __restrict__ Wsrc, const float* __restrict__ Wdst,
    const float* __restrict__ Wlin, int N)
{
    extern __shared__ float sm[];
    float* sWin = sm;
    float* sWs  = sWin + 4096;
    float* sWd  = sWs  + 4096;
    float* sWl  = sWd  + 4096;
    float* sb   = sWl  + 4096;
    float* xs   = sb + 64;
    float* hs   = xs + 64 * RS;
    const int tid = threadIdx.x;

    for (int i = tid; i < 4096; i += 256) {
        sWin[i] = Win[i]; sWs[i] = Wsrc[i]; sWd[i] = Wdst[i]; sWl[i] = Wlin[i];
    }
    if (tid < 64) sb[tid] = bin[tid];

    const int base = blockIdx.x * 64;
    for (int i = tid; i < 1024; i += 256) {
        int r = i >> 4, c4 = (i & 15) << 2;
        int row = base + r;
        float4 v = (row < N) ? *(const float4*)(x + (size_t)row * 64 + c4)
                             : make_float4(0.f, 0.f, 0.f, 0.f);
        *(float4*)(xs + r * RS + c4) = v;
    }
    __syncthreads();

    const int tr = tid >> 4, tc = tid & 15, r0 = tr * 4, c0 = tc * 4;
    float acc[4][4];

#pragma unroll
    for (int i = 0; i < 4; i++)
#pragma unroll
        for (int j = 0; j < 4; j++) acc[i][j] = sb[c0 + j];
    gemm64_acc(xs, sWin, r0, c0, acc);
#pragma unroll
    for (int i = 0; i < 4; i++)
#pragma unroll
        for (int j = 0; j < 4; j++) hs[(r0 + i) * RS + c0 + j] = fmaxf(acc[i][j], 0.f);
    __syncthreads();

#pragma unroll
    for (int i = 0; i < 4; i++)
#pragma unroll
        for (int j = 0; j < 4; j++) acc[i][j] = 0.f;
    gemm64_acc(hs, sWs, r0, c0, acc);
#pragma unroll
    for (int i = 0; i < 4; i++) {
        int row = base + r0 + i;
        if (row < N) *(float4*)(g_asrc + (size_t)row * 64 + c0) =
            make_float4(acc[i][0], acc[i][1], acc[i][2], acc[i][3]);
    }

#pragma unroll
    for (int i = 0; i < 4; i++)
#pragma unroll
        for (int j = 0; j < 4; j++) acc[i][j] = 0.f;
    gemm64_acc(hs, sWd, r0, c0, acc);
#pragma unroll
    for (int i = 0; i < 4; i++) {
        int row = base + r0 + i;
        if (row < N) *(float4*)(g_adst + (size_t)row * 64 + c0) =
            make_float4(acc[i][0], acc[i][1], acc[i][2], acc[i][3]);
    }

#pragma unroll
    for (int i = 0; i < 4; i++)
#pragma unroll
        for (int j = 0; j < 4; j++) acc[i][j] = 0.f;
    gemm64_acc(hs, sWl, r0, c0, acc);
#pragma unroll
    for (int i = 0; i < 4; i++) {
        int row = base + r0 + i;
        if (row < N) *(float4*)(g_v + (size_t)row * 64 + c0) =
            make_float4(acc[i][0], acc[i][1], acc[i][2], acc[i][3]);
    }
}

__global__ void __launch_bounds__(256) k_out(
    const float* __restrict__ x, const float* __restrict__ Wout,
    const float* __restrict__ bout, float* __restrict__ out, int N)
{
    extern __shared__ float sm[];
    float* sW = sm;
    float* sb = sW + 4096;
    float* As = sb + 64;
    const int tid = threadIdx.x;
    for (int i = tid; i < 4096; i += 256) sW[i] = Wout[i];
    if (tid < 64) sb[tid] = bout[tid];
    const int base = blockIdx.x * 64;
    for (int i = tid; i < 1024; i += 256) {
        int r = i >> 4, c4 = (i & 15) << 2;
        int row = base + r;
        float4 v = make_float4(0.f, 0.f, 0.f, 0.f);
        if (row < N) {
            float4 n4 = *(const float4*)(g_num  + (size_t)row * 64 + c4);
            float4 s4 = *(const float4*)(g_ssum + (size_t)row * 64 + c4);
            v = make_float4(n4.x / (s4.x + 1e-16f), n4.y / (s4.y + 1e-16f),
                            n4.z / (s4.z + 1e-16f), n4.w / (s4.w + 1e-16f));
        }
        *(float4*)(As + r * RS + c4) = v;
    }
    __syncthreads();
    const int tr = tid >> 4, tc = tid & 15, r0 = tr * 4, c0 = tc * 4;
    float acc[4][4];
#pragma unroll
    for (int i = 0; i < 4; i++)
#pragma unroll
        for (int j = 0; j < 4; j++) acc[i][j] = sb[c0 + j];
    gemm64_acc(As, sW, r0, c0, acc);
#pragma unroll
    for (int i = 0; i < 4; i++) {
        int row = base + r0 + i;
        if (row < N) {
            float4 res = *(const float4*)(x + (size_t)row * 64 + c0);
            *(float4*)(out + (size_t)row * 64 + c0) =
                make_float4(fmaxf(acc[i][0], 0.f) + res.x,
                            fmaxf(acc[i][1], 0.f) + res.y,
                            fmaxf(acc[i][2], 0.f) + res.z,
                            fmaxf(acc[i][3], 0.f) + res.w);
        }
    }
}

// ---------------- host ----------------
extern "C" void kernel_launch(void* const* d_in, const int* in_sizes, int n_in,
                              void* d_out, int out_size)
{
    const float* x    = (const float*)d_in[0];
    const float* pos  = (const float*)d_in[1];
    const int*   ei   = (const int*)  d_in[2];
    const float* Win  = (const float*)d_in[3];
    const float* bin  = (const float*)d_in[4];
    const float* Wout = (const float*)d_in[5];
    const float* bout = (const float*)d_in[6];
    const float* Wlin = (const float*)d_in[7];
    const float* Wsrc = (const float*)d_in[8];
    const float* Wdst = (const float*)d_in[9];
    const float* Wp1  = (const float*)d_in[10];
    const float* bp1  = (const float*)d_in[11];
    const float* Wp2  = (const float*)d_in[12];
    const float* bp2  = (const float*)d_in[13];
    const float* Wa1  = (const float*)d_in[14];
    const float* ba1  = (const float*)d_in[15];
    const float* Wa2  = (const float*)d_in[16];
    const float* ba2  = (const float*)d_in[17];

    const int N = in_sizes[0] / 64;
    const int E = in_sizes[2] / 2;

    void *p_ssum, *p_num;
    cudaGetSymbolAddress(&p_ssum, g_ssum);
    cudaGetSymbolAddress(&p_num,  g_num);
    cudaMemsetAsync(p_ssum, 0, (size_t)N * 64 * sizeof(float), 0);
    cudaMemsetAsync(p_num,  0, (size_t)N * 64 * sizeof(float), 0);

    const int smem_proj = (4 * 4096 + 64 + 2 * 64 * RS) * 4;
    const int smem_out  = (4096 + 64 + 64 * RS) * 4;

    cudaFuncSetAttribute(k_proj,    cudaFuncAttributeMaxDynamicSharedMemorySize, smem_proj);
    cudaFuncSetAttribute(k_edge_tc, cudaFuncAttributeMaxDynamicSharedMemorySize, SMEM_EDGE);

    const int ntile_n = (N + 63) / 64;
    k_proj<<<ntile_n, 256, smem_proj>>>(x, Win, bin, Wsrc, Wdst, Wlin, N);
    k_edge_tc<<<296, 256, SMEM_EDGE>>>(pos, ei, Wp1, bp1, Wp2, bp2, Wa1, ba1, Wa2, ba2, N, E);
    k_out<<<ntile_n, 256, smem_out>>>(x, Wout, bout, (float*)d_out, N);
}

// round 7
// speedup vs baseline: 4.6728x; 1.0678x over previous
#include <cuda_runtime.h>
#include <cuda_bf16.h>
#include <stdint.h>
#include <math.h>

#define F 64
#define N_CAP 50176

// ---------------- device scratch ----------------
__device__ float g_asrc[N_CAP * F];
__device__ float g_adst[N_CAP * F];
__device__ float g_v   [N_CAP * F];
__device__ float g_ssum[N_CAP * F];   // sum of exp(alpha) per dst
__device__ float g_num [N_CAP * F];   // sum of exp(alpha)*(v[src]+delta) per dst

// ---------------- mma.sync / ldmatrix helpers ----------------
__device__ __forceinline__ void ldsm4(uint32_t r[4], uint32_t addr) {
    asm volatile("ldmatrix.sync.aligned.m8n8.x4.shared.b16 {%0,%1,%2,%3}, [%4];"
                 : "=r"(r[0]), "=r"(r[1]), "=r"(r[2]), "=r"(r[3]) : "r"(addr));
}
__device__ __forceinline__ void ldsm4t(uint32_t r[4], uint32_t addr) {
    asm volatile("ldmatrix.sync.aligned.m8n8.x4.trans.shared.b16 {%0,%1,%2,%3}, [%4];"
                 : "=r"(r[0]), "=r"(r[1]), "=r"(r[2]), "=r"(r[3]) : "r"(addr));
}
__device__ __forceinline__ void mma16816(float d[4], const uint32_t a[4], uint32_t b0, uint32_t b1) {
    asm volatile("mma.sync.aligned.m16n8k16.row.col.f32.bf16.bf16.f32 "
                 "{%0,%1,%2,%3}, {%4,%5,%6,%7}, {%8,%9}, {%0,%1,%2,%3};"
                 : "+f"(d[0]), "+f"(d[1]), "+f"(d[2]), "+f"(d[3])
                 : "r"(a[0]), "r"(a[1]), "r"(a[2]), "r"(a[3]), "r"(b0), "r"(b1));
}
__device__ __forceinline__ uint32_t smem_u32(const void* p) {
    uint32_t a;
    asm("{ .reg .u64 t; cvta.to.shared.u64 t, %1; cvt.u32.u64 %0, t; }" : "=r"(a) : "l"(p));
    return a;
}
__device__ __forceinline__ void red4(float* p, float a, float b, float c, float d) {
    asm volatile("red.relaxed.gpu.global.add.v4.f32 [%0], {%1, %2, %3, %4};"
                 :: "l"(p), "f"(a), "f"(b), "f"(c), "f"(d) : "memory");
}
// split fp32 -> bf16 hi (at off) + lo (at off+128)
__device__ __forceinline__ void split1(char* base, uint32_t off, float w) {
    __nv_bfloat16 h = __float2bfloat16(w);
    __nv_bfloat16 l = __float2bfloat16(w - __bfloat162float(h));
    *(__nv_bfloat16*)(base + off) = h;
    *(__nv_bfloat16*)(base + off + 128) = l;
}
__device__ __forceinline__ void split2(char* base, uint32_t off, float a, float b) {
    __nv_bfloat162 h = __float22bfloat162_rn(make_float2(a, b));
    float2 hf = __bfloat1622float2(h);
    __nv_bfloat162 l = __float22bfloat162_rn(make_float2(a - hf.x, b - hf.y));
    *(__nv_bfloat162*)(base + off) = h;
    *(__nv_bfloat162*)(base + off + 128) = l;
}
// n-permutation: fragment col p -> logical col 16*((p>>1)&3) + 2*(p>>3) + (p&1)
__device__ __forceinline__ int nperm(int p) {
    return 16 * ((p >> 1) & 3) + 2 * (p >> 3) + (p & 1);
}

// A/B smem rows: [hi 128B][lo 128B][pad 16B] = 272B stride (conflict-free ldmatrix)
// one 64x64x64 GEMM stage (3-pass split: HH + HL + LH; LL dropped ~2^-16)
__device__ __forceinline__ void stage_mma(uint32_t aBase, uint32_t bBase,
                                          uint32_t lrow272, uint32_t lcolb, float acc[8][4])
{
#pragma unroll
    for (int kk = 0; kk < 64; kk += 16) {
        uint32_t aH[4], aL[4];
        uint32_t aaddr = aBase + lrow272 + kk * 2 + lcolb;
        ldsm4(aH, aaddr);
        ldsm4(aL, aaddr + 128);
#pragma unroll
        for (int np = 0; np < 4; np++) {
            uint32_t bH[4], bL[4];
            uint32_t baddr = bBase + kk * 272 + lrow272 + np * 32 + lcolb;
            ldsm4t(bH, baddr);
            ldsm4t(bL, baddr + 128);
            mma16816(acc[2 * np], aH, bH[0], bH[1]);
            mma16816(acc[2 * np], aH, bL[0], bL[1]);
            mma16816(acc[2 * np], aL, bH[0], bH[1]);
            mma16816(acc[2 * np + 1], aH, bH[2], bH[3]);
            mma16816(acc[2 * np + 1], aH, bL[2], bL[3]);
            mma16816(acc[2 * np + 1], aL, bH[2], bH[3]);
        }
    }
}
#define ZACC(acc) { _Pragma("unroll") for (int _i = 0; _i < 8; _i++) \
                    _Pragma("unroll") for (int _j = 0; _j < 4; _j++) (acc)[_i][_j] = 0.f; }

// ============================================================================
// K2: per-edge MLPs on tensor cores; accumulate e and e*(v[src]+delta)
// ============================================================================
#define E_BP1 0
#define E_BP2 256
#define E_BA1 512
#define E_BA2 768
#define E_WP1 1024
#define E_A   2560
#define E_B0  37376
#define E_B1  54784
#define E_B2  72192
#define SMEM_EDGE 89600

__global__ void __launch_bounds__(256, 2) k_edge_tc(
    const float* __restrict__ pos, const int* __restrict__ ei,
    const float* __restrict__ Wp1, const float* __restrict__ bp1,
    const float* __restrict__ Wp2, const float* __restrict__ bp2,
    const float* __restrict__ Wa1, const float* __restrict__ ba1,
    const float* __restrict__ Wa2, const float* __restrict__ ba2,
    int N, int E)
{
    extern __shared__ char smem[];
    const uint32_t sb = smem_u32(smem);
    const int tid  = threadIdx.x;
    const int wid  = tid >> 5;
    const int lane = tid & 31;
    const int wb   = wid * 16;
    const int g    = lane >> 2;
    const int tig  = lane & 3;

    float* sbp1 = (float*)(smem + E_BP1);
    float* sbp2 = (float*)(smem + E_BP2);
    float* sba1 = (float*)(smem + E_BA1);
    float* sba2 = (float*)(smem + E_BA2);
    float* sWp1 = (float*)(smem + E_WP1);

    if (tid < 64) { sbp1[tid] = bp1[tid]; sbp2[tid] = bp2[tid]; sba1[tid] = ba1[tid]; sba2[tid] = ba2[tid]; }
    for (int i = tid; i < 384; i += 256) sWp1[i] = Wp1[i];
    for (int idx = tid; idx < 4096; idx += 256) {
        int k = idx >> 6, p = idx & 63;
        int Lp = nperm(p);
        uint32_t off = (uint32_t)k * 272 + (uint32_t)p * 2;
        split1(smem + E_B0, off, Wp2[k * 64 + Lp]);
        split1(smem + E_B1, off, Wa1[k * 64 + p]);
        split1(smem + E_B2, off, Wa2[k * 64 + Lp]);
    }
    __syncthreads();

    const int TOT = N + E;
    const int NT  = (TOT + 127) >> 7;
    const uint32_t lrow272 = (uint32_t)((lane & 7) + 8 * ((lane >> 3) & 1)) * 272;
    const uint32_t lcolb   = (uint32_t)((lane >> 4) & 1) * 16;
    const uint32_t aBase   = sb + E_A + (uint32_t)wb * 272;
    char* smA = smem + E_A;

    for (int tile = blockIdx.x; tile < NT; tile += gridDim.x) {
        const int tbase = tile << 7;

        // ---- hidden1 = relu(posdiff @ Wp1 + bp1) -> A ----
        {
            int rh = wb + (lane >> 1);
            int eidh = tbase + rh;
            int sh = 0, dh = 0;
            if (eidh < TOT) {
                if (eidh < E) { sh = ei[eidh]; dh = ei[E + eidh]; }
                else          { sh = dh = eidh - E; }
            }
            float p6[6];
#pragma unroll
            for (int k = 0; k < 6; k++) p6[k] = pos[dh * 6 + k] - pos[sh * 6 + k];
            const int cbase = 32 * (lane & 1);
            const uint32_t rowb = (uint32_t)rh * 272;
#pragma unroll
            for (int cc = 0; cc < 32; cc += 2) {
                int c = cbase + cc;
                float h0 = sbp1[c], h1 = sbp1[c + 1];
#pragma unroll
                for (int k = 0; k < 6; k++) {
                    h0 = fmaf(p6[k], sWp1[k * 64 + c], h0);
                    h1 = fmaf(p6[k], sWp1[k * 64 + c + 1], h1);
                }
                split2(smA, rowb + c * 2, fmaxf(h0, 0.f), fmaxf(h1, 0.f));
            }
        }
        __syncwarp();

        const int er1 = wb + g, er2 = er1 + 8;
        const int eid1 = tbase + er1, eid2 = tbase + er2;
        int s1 = 0, d1 = 0, s2 = 0, d2 = 0;
        if (eid1 < TOT) { if (eid1 < E) { s1 = ei[eid1]; d1 = ei[E + eid1]; } else s1 = d1 = eid1 - E; }
        if (eid2 < TOT) { if (eid2 < E) { s2 = ei[eid2]; d2 = ei[E + eid2]; } else s2 = d2 = eid2 - E; }

        float acc[8][4];
        ZACC(acc);

        // ---- stage 1: delta (n-permuted) ----
        stage_mma(aBase, sb + E_B0, lrow272, lcolb, acc);
        __syncwarp();

        float tvd1[16], tvd2[16];
        {
            const uint32_t rowb1 = (uint32_t)er1 * 272, rowb2 = (uint32_t)er2 * 272;
#pragma unroll
            for (int q = 0; q < 4; q++) {
                const int c = 16 * tig + 4 * q;
                {
                    float4 ad = *(const float4*)(g_adst + (size_t)d1 * 64 + c);
                    float4 as = *(const float4*)(g_asrc + (size_t)s1 * 64 + c);
                    float4 vv = *(const float4*)(g_v    + (size_t)s1 * 64 + c);
                    float e0 = fmaxf(acc[2 * q][0] + sbp2[c + 0], 0.f);
                    float e1 = fmaxf(acc[2 * q][1] + sbp2[c + 1], 0.f);
                    float e2 = fmaxf(acc[2 * q + 1][0] + sbp2[c + 2], 0.f);
                    float e3 = fmaxf(acc[2 * q + 1][1] + sbp2[c + 3], 0.f);
                    split2(smA, rowb1 + c * 2,     ad.x - as.x + e0, ad.y - as.y + e1);
                    split2(smA, rowb1 + c * 2 + 4, ad.z - as.z + e2, ad.w - as.w + e3);
                    tvd1[4 * q + 0] = vv.x + e0; tvd1[4 * q + 1] = vv.y + e1;
                    tvd1[4 * q + 2] = vv.z + e2; tvd1[4 * q + 3] = vv.w + e3;
                }
                {
                    float4 ad = *(const float4*)(g_adst + (size_t)d2 * 64 + c);
                    float4 as = *(const float4*)(g_asrc + (size_t)s2 * 64 + c);
                    float4 vv = *(const float4*)(g_v    + (size_t)s2 * 64 + c);
                    float e0 = fmaxf(acc[2 * q][2] + sbp2[c + 0], 0.f);
                    float e1 = fmaxf(acc[2 * q][3] + sbp2[c + 1], 0.f);
                    float e2 = fmaxf(acc[2 * q + 1][2] + sbp2[c + 2], 0.f);
                    float e3 = fmaxf(acc[2 * q + 1][3] + sbp2[c + 3], 0.f);
                    split2(smA, rowb2 + c * 2,     ad.x - as.x + e0, ad.y - as.y + e1);
                    split2(smA, rowb2 + c * 2 + 4, ad.z - as.z + e2, ad.w - as.w + e3);
                    tvd2[4 * q + 0] = vv.x + e0; tvd2[4 * q + 1] = vv.y + e1;
                    tvd2[4 * q + 2] = vv.z + e2; tvd2[4 * q + 3] = vv.w + e3;
                }
            }
        }
        __syncwarp();

        // ---- stage 2: hidden2 (identity n) ----
        ZACC(acc);
        stage_mma(aBase, sb + E_B1, lrow272, lcolb, acc);
        __syncwarp();
        {
            const uint32_t rowb1 = (uint32_t)er1 * 272, rowb2 = (uint32_t)er2 * 272;
#pragma unroll
            for (int nt = 0; nt < 8; nt++) {
                const int c = 8 * nt + 2 * tig;
                split2(smA, rowb1 + c * 2, fmaxf(acc[nt][0] + sba1[c], 0.f),
                                           fmaxf(acc[nt][1] + sba1[c + 1], 0.f));
                split2(smA, rowb2 + c * 2, fmaxf(acc[nt][2] + sba1[c], 0.f),
                                           fmaxf(acc[nt][3] + sba1[c + 1], 0.f));
            }
        }
        __syncwarp();

        // ---- stage 3: alpha (n-permuted); e=exp; scatter ----
        ZACC(acc);
        stage_mma(aBase, sb + E_B2, lrow272, lcolb, acc);
        __syncwarp();
#pragma unroll
        for (int q = 0; q < 4; q++) {
            const int c = 16 * tig + 4 * q;
            if (eid1 < TOT) {
                float e0 = __expf(fmaxf(acc[2 * q][0] + sba2[c + 0], 0.f));
                float e1 = __expf(fmaxf(acc[2 * q][1] + sba2[c + 1], 0.f));
                float e2 = __expf(fmaxf(acc[2 * q + 1][0] + sba2[c + 2], 0.f));
                float e3 = __expf(fmaxf(acc[2 * q + 1][1] + sba2[c + 3], 0.f));
                red4(g_ssum + (size_t)d1 * 64 + c, e0, e1, e2, e3);
                red4(g_num  + (size_t)d1 * 64 + c, e0 * tvd1[4 * q + 0], e1 * tvd1[4 * q + 1],
                                                   e2 * tvd1[4 * q + 2], e3 * tvd1[4 * q + 3]);
            }
            if (eid2 < TOT) {
                float e0 = __expf(fmaxf(acc[2 * q][2] + sba2[c + 0], 0.f));
                float e1 = __expf(fmaxf(acc[2 * q][3] + sba2[c + 1], 0.f));
                float e2 = __expf(fmaxf(acc[2 * q + 1][2] + sba2[c + 2], 0.f));
                float e3 = __expf(fmaxf(acc[2 * q + 1][3] + sba2[c + 3], 0.f));
                red4(g_ssum + (size_t)d2 * 64 + c, e0, e1, e2, e3);
                red4(g_num  + (size_t)d2 * 64 + c, e0 * tvd2[4 * q + 0], e1 * tvd2[4 * q + 1],
                                                   e2 * tvd2[4 * q + 2], e3 * tvd2[4 * q + 3]);
            }
        }
        __syncwarp();
    }
}

// ============================================================================
// K1 (tensor-core): h = relu(x@Win+b); a_src/a_dst/v = h @ {Wsrc,Wdst,Wlin}
// ============================================================================
#define P_BIN 0
#define P_A    1024
#define P_BW   35840   // Win (identity n)
#define P_BS   53248   // Wsrc (n-perm)
#define P_BD   70656   // Wdst (n-perm)
#define P_BL   88064   // Wlin (n-perm)
#define SMEM_PROJ 105472

__global__ void __launch_bounds__(256, 2) k_proj_tc(
    const float* __restrict__ x,
    const float* __restrict__ Win, const float* __restrict__ bin,
    const float* __restrict__ Wsrc, const float* __restrict__ Wdst,
    const float* __restrict__ Wlin, int N)
{
    extern __shared__ char smem[];
    const uint32_t sb = smem_u32(smem);
    const int tid  = threadIdx.x;
    const int wid  = tid >> 5;
    const int lane = tid & 31;
    const int wb   = wid * 16;
    const int g    = lane >> 2;
    const int tig  = lane & 3;

    float* sbin = (float*)(smem + P_BIN);
    if (tid < 64) sbin[tid] = bin[tid];
    for (int idx = tid; idx < 4096; idx += 256) {
        int k = idx >> 6, p = idx & 63;
        int Lp = nperm(p);
        uint32_t off = (uint32_t)k * 272 + (uint32_t)p * 2;
        split1(smem + P_BW, off, Win[idx]);
        split1(smem + P_BS, off, Wsrc[k * 64 + Lp]);
        split1(smem + P_BD, off, Wdst[k * 64 + Lp]);
        split1(smem + P_BL, off, Wlin[k * 64 + Lp]);
    }
    __syncthreads();

    const uint32_t lrow272 = (uint32_t)((lane & 7) + 8 * ((lane >> 3) & 1)) * 272;
    const uint32_t lcolb   = (uint32_t)((lane >> 4) & 1) * 16;
    const uint32_t aBase   = sb + P_A + (uint32_t)wb * 272;
    char* smA = smem + P_A;

    const int tbase = blockIdx.x << 7;

    // load x rows -> A (bf16 split)
    {
        int rh = wb + (lane >> 1);
        int row = tbase + rh;
        const int cbase = 32 * (lane & 1);
        const uint32_t rowb = (uint32_t)rh * 272;
#pragma unroll
        for (int cc = 0; cc < 32; cc += 4) {
            int c = cbase + cc;
            float4 v = (row < N) ? *(const float4*)(x + (size_t)row * 64 + c)
                                 : make_float4(0.f, 0.f, 0.f, 0.f);
            split2(smA, rowb + c * 2,     v.x, v.y);
            split2(smA, rowb + c * 2 + 4, v.z, v.w);
        }
    }
    __syncwarp();

    const int er1 = wb + g, er2 = er1 + 8;
    const int row1 = tbase + er1, row2 = tbase + er2;

    float acc[8][4];
    // h = relu(x@Win + bin) -> A (identity n epilogue)
    ZACC(acc);
    stage_mma(aBase, sb + P_BW, lrow272, lcolb, acc);
    __syncwarp();
    {
        const uint32_t rowb1 = (uint32_t)er1 * 272, rowb2 = (uint32_t)er2 * 272;
#pragma unroll
        for (int nt = 0; nt < 8; nt++) {
            const int c = 8 * nt + 2 * tig;
            split2(smA, rowb1 + c * 2, fmaxf(acc[nt][0] + sbin[c], 0.f),
                                       fmaxf(acc[nt][1] + sbin[c + 1], 0.f));
            split2(smA, rowb2 + c * 2, fmaxf(acc[nt][2] + sbin[c], 0.f),
                                       fmaxf(acc[nt][3] + sbin[c + 1], 0.f));
        }
    }
    __syncwarp();

    float* outs[3] = { g_asrc, g_adst, g_v };
    const uint32_t boffs[3] = { P_BS, P_BD, P_BL };
#pragma unroll
    for (int t = 0; t < 3; t++) {
        ZACC(acc);
        stage_mma(aBase, sb + boffs[t], lrow272, lcolb, acc);
        __syncwarp();
#pragma unroll
        for (int q = 0; q < 4; q++) {
            const int c = 16 * tig + 4 * q;
            if (row1 < N)
                *(float4*)(outs[t] + (size_t)row1 * 64 + c) =
                    make_float4(acc[2 * q][0], acc[2 * q][1], acc[2 * q + 1][0], acc[2 * q + 1][1]);
            if (row2 < N)
                *(float4*)(outs[t] + (size_t)row2 * 64 + c) =
                    make_float4(acc[2 * q][2], acc[2 * q][3], acc[2 * q + 1][2], acc[2 * q + 1][3]);
        }
        __syncwarp();
    }
}

// ============================================================================
// K3 (tensor-core): out = relu((num/ssum) @ Wout + bout) + x
// ============================================================================
#define O_BOUT 0
#define O_A    1024
#define O_BW   35840  // Wout (n-perm)
#define SMEM_OUT 53248

__global__ void __launch_bounds__(256, 2) k_out_tc(
    const float* __restrict__ x, const float* __restrict__ Wout,
    const float* __restrict__ bout, float* __restrict__ out, int N)
{
    extern __shared__ char smem[];
    const uint32_t sb = smem_u32(smem);
    const int tid  = threadIdx.x;
    const int wid  = tid >> 5;
    const int lane = tid & 31;
    const int wb   = wid * 16;
    const int g    = lane >> 2;
    const int tig  = lane & 3;

    float* sbo = (float*)(smem + O_BOUT);
    if (tid < 64) sbo[tid] = bout[tid];
    for (int idx = tid; idx < 4096; idx += 256) {
        int k = idx >> 6, p = idx & 63;
        uint32_t off = (uint32_t)k * 272 + (uint32_t)p * 2;
        split1(smem + O_BW, off, Wout[k * 64 + nperm(p)]);
    }
    __syncthreads();

    const uint32_t lrow272 = (uint32_t)((lane & 7) + 8 * ((lane >> 3) & 1)) * 272;
    const uint32_t lcolb   = (uint32_t)((lane >> 4) & 1) * 16;
    const uint32_t aBase   = sb + O_A + (uint32_t)wb * 272;
    char* smA = smem + O_A;

    const int tbase = blockIdx.x << 7;
    {
        int rh = wb + (lane >> 1);
        int row = tbase + rh;
        const int cbase = 32 * (lane & 1);
        const uint32_t rowb = (uint32_t)rh * 272;
#pragma unroll
        for (int cc = 0; cc < 32; cc += 4) {
            int c = cbase + cc;
            float4 v = make_float4(0.f, 0.f, 0.f, 0.f);
            if (row < N) {
                float4 n4 = *(const float4*)(g_num  + (size_t)row * 64 + c);
                float4 s4 = *(const float4*)(g_ssum + (size_t)row * 64 + c);
                v = make_float4(n4.x / (s4.x + 1e-16f), n4.y / (s4.y + 1e-16f),
                                n4.z / (s4.z + 1e-16f), n4.w / (s4.w + 1e-16f));
            }
            split2(smA, rowb + c * 2,     v.x, v.y);
            split2(smA, rowb + c * 2 + 4, v.z, v.w);
        }
    }
    __syncwarp();

    const int er1 = wb + g, er2 = er1 + 8;
    const int row1 = tbase + er1, row2 = tbase + er2;

    float acc[8][4];
    ZACC(acc);
    stage_mma(aBase, sb + O_BW, lrow272, lcolb, acc);
    __syncwarp();
#pragma unroll
    for (int q = 0; q < 4; q++) {
        const int c = 16 * tig + 4 * q;
        if (row1 < N) {
            float4 r = *(const float4*)(x + (size_t)row1 * 64 + c);
            *(float4*)(out + (size_t)row1 * 64 + c) =
                make_float4(fmaxf(acc[2 * q][0] + sbo[c + 0], 0.f) + r.x,
                            fmaxf(acc[2 * q][1] + sbo[c + 1], 0.f) + r.y,
                            fmaxf(acc[2 * q + 1][0] + sbo[c + 2], 0.f) + r.z,
                            fmaxf(acc[2 * q + 1][1] + sbo[c + 3], 0.f) + r.w);
        }
        if (row2 < N) {
            float4 r = *(const float4*)(x + (size_t)row2 * 64 + c);
            *(float4*)(out + (size_t)row2 * 64 + c) =
                make_float4(fmaxf(acc[2 * q][2] + sbo[c + 0], 0.f) + r.x,
                            fmaxf(acc[2 * q][3] + sbo[c + 1], 0.f) + r.y,
                            fmaxf(acc[2 * q + 1][2] + sbo[c + 2], 0.f) + r.z,
                            fmaxf(acc[2 * q + 1][3] + sbo[c + 3], 0.f) + r.w);
        }
    }
}

// ---------------- host ----------------
extern "C" void kernel_launch(void* const* d_in, const int* in_sizes, int n_in,
                              void* d_out, int out_size)
{
    const float* x    = (const float*)d_in[0];
    const float* pos  = (const float*)d_in[1];
    const int*   ei   = (const int*)  d_in[2];
    const float* Win  = (const float*)d_in[3];
    const float* bin  = (const float*)d_in[4];
    const float* Wout = (const float*)d_in[5];
    const float* bout = (const float*)d_in[6];
    const float* Wlin = (const float*)d_in[7];
    const float* Wsrc = (const float*)d_in[8];
    const float* Wdst = (const float*)d_in[9];
    const float* Wp1  = (const float*)d_in[10];
    const float* bp1  = (const float*)d_in[11];
    const float* Wp2  = (const float*)d_in[12];
    const float* bp2  = (const float*)d_in[13];
    const float* Wa1  = (const float*)d_in[14];
    const float* ba1  = (const float*)d_in[15];
    const float* Wa2  = (const float*)d_in[16];
    const float* ba2  = (const float*)d_in[17];

    const int N = in_sizes[0] / 64;
    const int E = in_sizes[2] / 2;

    void *p_ssum, *p_num;
    cudaGetSymbolAddress(&p_ssum, g_ssum);
    cudaGetSymbolAddress(&p_num,  g_num);
    cudaMemsetAsync(p_ssum, 0, (size_t)N * 64 * sizeof(float), 0);
    cudaMemsetAsync(p_num,  0, (size_t)N * 64 * sizeof(float), 0);

    cudaFuncSetAttribute(k_proj_tc, cudaFuncAttributeMaxDynamicSharedMemorySize, SMEM_PROJ);
    cudaFuncSetAttribute(k_edge_tc, cudaFuncAttributeMaxDynamicSharedMemorySize, SMEM_EDGE);
    cudaFuncSetAttribute(k_out_tc,  cudaFuncAttributeMaxDynamicSharedMemorySize, SMEM_OUT);

    const int ntile = (N + 127) / 128;
    k_proj_tc<<<ntile, 256, SMEM_PROJ>>>(x, Win, bin, Wsrc, Wdst, Wlin, N);
    k_edge_tc<<<296, 256, SMEM_EDGE>>>(pos, ei, Wp1, bp1, Wp2, bp2, Wa1, ba1, Wa2, ba2, N, E);
    k_out_tc<<<ntile, 256, SMEM_OUT>>>(x, Wout, bout, (float*)d_out, N);
}